// round 11
// baseline (speedup 1.0000x reference)
#include <cuda_runtime.h>
#include <cuda_fp16.h>

#define NMAX 100000
#define EMAX 1600000
#define CIN  128

// ---------------- scratch (device globals; no allocation allowed) ----------
// g_deg holds IN-degree (no self loop); zero at entry of every call
// (zero-initialized at load; self-cleaned by final agg each call).
__device__ int   g_deg[NMAX];
__device__ int   g_offs[NMAX];         // CSR start (block-atomic bases; end = start+indeg)
__device__ int   g_cursor[NMAX];
__device__ int   g_base;               // atomic base for block scan (self-cleaned)
__device__ __align__(16) int2   g_csr[EMAX];        // {src, float bits of dinv[src]}
__device__ __align__(16) __half g_h[NMAX * 64];     // gemm output, fp16 (layer3 pitch 40)
__device__ __align__(16) __half g_out_h[NMAX * 64]; // agg output, fp16, RELU APPLIED

// ---------------- prep -------------------------------------------------------
// 4 edges per thread for MLP on the atomic chain.
__global__ void k_count(const int* __restrict__ ei, int E) {
    int i = blockIdx.x * blockDim.x + threadIdx.x;
    int e4 = i * 4;
    if (e4 >= E) return;
    if (((E & 3) == 0) && (e4 + 4 <= E)) {
        int4 d = *(const int4*)&ei[E + e4];
        atomicAdd(&g_deg[d.x], 1);
        atomicAdd(&g_deg[d.y], 1);
        atomicAdd(&g_deg[d.z], 1);
        atomicAdd(&g_deg[d.w], 1);
    } else {
        int lim = (e4 + 4 < E) ? e4 + 4 : E;
        for (int e = e4; e < lim; e++) atomicAdd(&g_deg[ei[E + e]], 1);
    }
}

// single-kernel scan of in-degree: block-local scan + atomic base.
__global__ void k_scan(int n) {
    __shared__ int wsum[8];
    __shared__ int sbase;
    int t = threadIdx.x;
    int lane = t & 31, wid = t >> 5;
    int base = blockIdx.x * 1024;
    int loc[4];
    int v = 0;
    #pragma unroll
    for (int j = 0; j < 4; j++) {
        int i = base + t * 4 + j;
        loc[j] = (i < n) ? g_deg[i] : 0;
        v += loc[j];
    }
    int s = v;
    #pragma unroll
    for (int off = 1; off < 32; off <<= 1) {
        int y = __shfl_up_sync(0xffffffffu, s, off);
        if (lane >= off) s += y;
    }
    if (lane == 31) wsum[wid] = s;
    __syncthreads();
    if (t == 0) {
        int acc = 0;
        #pragma unroll
        for (int w = 0; w < 8; w++) { int x2 = wsum[w]; wsum[w] = acc; acc += x2; }
        sbase = atomicAdd(&g_base, acc);
    }
    __syncthreads();
    int run = sbase + wsum[wid] + s - v;
    #pragma unroll
    for (int j = 0; j < 4; j++) {
        int i = base + t * 4 + j;
        if (i < n) {
            g_offs[i] = run;
            g_cursor[i] = run;
            run += loc[j];
        }
    }
}

// CSR fill: {src, dinv[src]}; 4 edges/thread for MLP.
__global__ void k_fill_csr(const int* __restrict__ ei, int E) {
    int i = blockIdx.x * blockDim.x + threadIdx.x;
    int e4 = i * 4;
    if (e4 >= E) return;
    if (((E & 3) == 0) && (e4 + 4 <= E)) {
        int4 sv = *(const int4*)&ei[e4];
        int4 dv = *(const int4*)&ei[E + e4];
        float i0 = rsqrtf((float)(g_deg[sv.x] + 1));
        float i1 = rsqrtf((float)(g_deg[sv.y] + 1));
        float i2 = rsqrtf((float)(g_deg[sv.z] + 1));
        float i3 = rsqrtf((float)(g_deg[sv.w] + 1));
        int p0 = atomicAdd(&g_cursor[dv.x], 1);
        int p1 = atomicAdd(&g_cursor[dv.y], 1);
        int p2 = atomicAdd(&g_cursor[dv.z], 1);
        int p3 = atomicAdd(&g_cursor[dv.w], 1);
        g_csr[p0] = make_int2(sv.x, __float_as_int(i0));
        g_csr[p1] = make_int2(sv.y, __float_as_int(i1));
        g_csr[p2] = make_int2(sv.z, __float_as_int(i2));
        g_csr[p3] = make_int2(sv.w, __float_as_int(i3));
    } else {
        int lim = (e4 + 4 < E) ? e4 + 4 : E;
        for (int e = e4; e < lim; e++) {
            int s = ei[e];
            int d = ei[E + e];
            float ds = rsqrtf((float)(g_deg[s] + 1));
            int pos = atomicAdd(&g_cursor[d], 1);
            g_csr[pos] = make_int2(s, __float_as_int(ds));
        }
    }
}

// ---------------- layer-1 GEMM (fp32 SIMT persistent) ------------------------
// g_h(fp16) = x(fp32) @ W1. k-vectorized: 4 k per step, LDS.128 A-loads.
__global__ void k_gemm1(const float* __restrict__ X, const float* __restrict__ W,
                        int n) {
    constexpr int K = 128, COUT = 64, BM = 32;
    constexpr int KP = K + 4;                // pad: de-conflict 4-row A loads
    constexpr int NT = COUT / 4;             // 16
    constexpr int NTHREADS = NT * (BM / 4);  // 128
    __shared__ float ws[K][COUT];
    __shared__ float xs[BM][KP];

    int t = threadIdx.x;
    constexpr int WF4 = K * COUT / 4;
    float* wsf = &ws[0][0];
    for (int idx = t; idx < WF4; idx += NTHREADS)
        *(float4*)&wsf[idx * 4] = *(const float4*)&W[idx * 4];

    int nidx = t % NT;
    int midx = t / NT;
    int ntiles = (n + BM - 1) / BM;

    for (int tile = blockIdx.x; tile < ntiles; tile += gridDim.x) {
        int base = tile * BM;
        __syncthreads();
        constexpr int XF4 = BM * K / 4;
        for (int idx = t; idx < XF4; idx += NTHREADS) {
            int r = idx / (K / 4), kc = idx % (K / 4);
            int gr = base + r;
            float4 v = make_float4(0.f, 0.f, 0.f, 0.f);
            if (gr < n) v = *(const float4*)&X[(size_t)gr * K + kc * 4];
            *(float4*)&xs[r][kc * 4] = v;
        }
        __syncthreads();

        float acc[4][4] = {};
        #pragma unroll 2
        for (int k4 = 0; k4 < K / 4; k4++) {
            float4 a0 = *(const float4*)&xs[midx * 4 + 0][k4 * 4];
            float4 a1 = *(const float4*)&xs[midx * 4 + 1][k4 * 4];
            float4 a2 = *(const float4*)&xs[midx * 4 + 2][k4 * 4];
            float4 a3 = *(const float4*)&xs[midx * 4 + 3][k4 * 4];
            #pragma unroll
            for (int kk = 0; kk < 4; kk++) {
                float4 b4 = *(const float4*)&ws[k4 * 4 + kk][nidx * 4];
                float v0 = (&a0.x)[kk];
                float v1 = (&a1.x)[kk];
                float v2 = (&a2.x)[kk];
                float v3 = (&a3.x)[kk];
                acc[0][0] += v0 * b4.x; acc[0][1] += v0 * b4.y; acc[0][2] += v0 * b4.z; acc[0][3] += v0 * b4.w;
                acc[1][0] += v1 * b4.x; acc[1][1] += v1 * b4.y; acc[1][2] += v1 * b4.z; acc[1][3] += v1 * b4.w;
                acc[2][0] += v2 * b4.x; acc[2][1] += v2 * b4.y; acc[2][2] += v2 * b4.z; acc[2][3] += v2 * b4.w;
                acc[3][0] += v3 * b4.x; acc[3][1] += v3 * b4.y; acc[3][2] += v3 * b4.z; acc[3][3] += v3 * b4.w;
            }
        }

        #pragma unroll
        for (int i = 0; i < 4; i++) {
            int gr = base + midx * 4 + i;
            if (gr < n) {
                __half2 p0 = __floats2half2_rn(acc[i][0], acc[i][1]);
                __half2 p1 = __floats2half2_rn(acc[i][2], acc[i][3]);
                uint2 u = make_uint2(*(unsigned*)&p0, *(unsigned*)&p1);
                *(uint2*)&g_h[(size_t)gr * COUT + nidx * 4] = u;
            }
        }
    }
}

// ---------------- layers 2/3 GEMM (SIMT persistent, fp16 in/out) ------------
// g_h(fp16) = g_out_h(fp16, relu'd) @ W(fp32). Same k-vectorized loop.
template <int K, int COUT>
__global__ void k_gemm_h(const float* __restrict__ W, int n) {
    constexpr int BM = 32;
    constexpr int KP = K + 4;
    constexpr int NT = COUT / 4;
    constexpr int MT = BM / 4;               // 8
    constexpr int NTHREADS = NT * MT;
    __shared__ float ws[K][COUT];
    __shared__ float xs[BM][KP];

    int t = threadIdx.x;
    constexpr int WF4 = K * COUT / 4;
    float* wsf = &ws[0][0];
    for (int idx = t; idx < WF4; idx += NTHREADS)
        *(float4*)&wsf[idx * 4] = *(const float4*)&W[idx * 4];

    int nidx = t % NT;
    int midx = t / NT;
    int ntiles = (n + BM - 1) / BM;

    for (int tile = blockIdx.x; tile < ntiles; tile += gridDim.x) {
        int base = tile * BM;
        __syncthreads();
        constexpr int XF4 = BM * K / 4;
        for (int idx = t; idx < XF4; idx += NTHREADS) {
            int r = idx / (K / 4), kc = idx % (K / 4);
            int gr = base + r;
            float4 v = make_float4(0.f, 0.f, 0.f, 0.f);
            if (gr < n) {
                uint2 u = *(const uint2*)&g_out_h[(size_t)gr * K + kc * 4];
                float2 f01 = __half22float2(*(__half2*)&u.x);
                float2 f23 = __half22float2(*(__half2*)&u.y);
                v = make_float4(f01.x, f01.y, f23.x, f23.y);
            }
            *(float4*)&xs[r][kc * 4] = v;
        }
        __syncthreads();

        float acc[4][4] = {};
        #pragma unroll 2
        for (int k4 = 0; k4 < K / 4; k4++) {
            float4 a0 = *(const float4*)&xs[midx * 4 + 0][k4 * 4];
            float4 a1 = *(const float4*)&xs[midx * 4 + 1][k4 * 4];
            float4 a2 = *(const float4*)&xs[midx * 4 + 2][k4 * 4];
            float4 a3 = *(const float4*)&xs[midx * 4 + 3][k4 * 4];
            #pragma unroll
            for (int kk = 0; kk < 4; kk++) {
                float4 b4 = *(const float4*)&ws[k4 * 4 + kk][nidx * 4];
                float v0 = (&a0.x)[kk];
                float v1 = (&a1.x)[kk];
                float v2 = (&a2.x)[kk];
                float v3 = (&a3.x)[kk];
                acc[0][0] += v0 * b4.x; acc[0][1] += v0 * b4.y; acc[0][2] += v0 * b4.z; acc[0][3] += v0 * b4.w;
                acc[1][0] += v1 * b4.x; acc[1][1] += v1 * b4.y; acc[1][2] += v1 * b4.z; acc[1][3] += v1 * b4.w;
                acc[2][0] += v2 * b4.x; acc[2][1] += v2 * b4.y; acc[2][2] += v2 * b4.z; acc[2][3] += v2 * b4.w;
                acc[3][0] += v3 * b4.x; acc[3][1] += v3 * b4.y; acc[3][2] += v3 * b4.z; acc[3][3] += v3 * b4.w;
            }
        }

        #pragma unroll
        for (int i = 0; i < 4; i++) {
            int gr = base + midx * 4 + i;
            if (gr < n) {
                __half2 p0 = __floats2half2_rn(acc[i][0], acc[i][1]);
                __half2 p1 = __floats2half2_rn(acc[i][2], acc[i][3]);
                uint2 u = make_uint2(*(unsigned*)&p0, *(unsigned*)&p1);
                *(uint2*)&g_h[(size_t)gr * COUT + nidx * 4] = u;
            }
        }
    }
}

// ---------------- aggregation ------------------------------------------------
// out = b + dinv_d * (dinv_d*h[node] + sum_s dinv_s*h[s])
// one warp per node; lane owns 2 channels; edge record broadcast-loaded;
// unroll 4. FINAL: fp32 OUT arg + self-clean g_deg/g_base; else relu->fp16.
template <int C, bool FINAL>
__global__ void k_agg(const float* __restrict__ b, float* __restrict__ OUTarg,
                      int n) {
    const __half* H = (const __half*)g_h;

    int node = (blockIdx.x * blockDim.x + threadIdx.x) >> 5;
    int lane = threadIdx.x & 31;
    if (node >= n) return;
    int c = lane * 2;
    bool act = (c < C);

    int indeg = g_deg[node];
    float dinv = rsqrtf((float)(indeg + 1));

    float2 acc = make_float2(0.f, 0.f);
    if (act) {
        float2 hv = __half22float2(*(const __half2*)&H[(size_t)node * C + c]);
        acc.x = dinv * hv.x;
        acc.y = dinv * hv.y;
    }

    int e0 = g_offs[node];
    int e1 = e0 + indeg;
    int e = e0;
    for (; e + 4 <= e1; e += 4) {
        int2 r0 = g_csr[e];
        int2 r1 = g_csr[e + 1];
        int2 r2 = g_csr[e + 2];
        int2 r3 = g_csr[e + 3];
        if (act) {
            float2 h0 = __half22float2(*(const __half2*)&H[(size_t)r0.x * C + c]);
            float2 h1 = __half22float2(*(const __half2*)&H[(size_t)r1.x * C + c]);
            float2 h2 = __half22float2(*(const __half2*)&H[(size_t)r2.x * C + c]);
            float2 h3 = __half22float2(*(const __half2*)&H[(size_t)r3.x * C + c]);
            float n0 = __int_as_float(r0.y), n1 = __int_as_float(r1.y);
            float n2 = __int_as_float(r2.y), n3 = __int_as_float(r3.y);
            acc.x += n0 * h0.x; acc.y += n0 * h0.y;
            acc.x += n1 * h1.x; acc.y += n1 * h1.y;
            acc.x += n2 * h2.x; acc.y += n2 * h2.y;
            acc.x += n3 * h3.x; acc.y += n3 * h3.y;
        }
    }
    for (; e < e1; e++) {
        int2 r = g_csr[e];
        if (act) {
            float2 hv = __half22float2(*(const __half2*)&H[(size_t)r.x * C + c]);
            float nn = __int_as_float(r.y);
            acc.x += nn * hv.x; acc.y += nn * hv.y;
        }
    }
    if (act) {
        float ox = b[c]     + dinv * acc.x;
        float oy = b[c + 1] + dinv * acc.y;
        if (FINAL) {
            *(float2*)&OUTarg[(size_t)node * C + c] = make_float2(ox, oy);
        } else {
            ox = fmaxf(ox, 0.f);
            oy = fmaxf(oy, 0.f);
            __half2 p = __floats2half2_rn(ox, oy);
            *(unsigned*)&g_out_h[(size_t)node * C + c] = *(unsigned*)&p;
        }
    }
    if (FINAL) {
        // self-clean for next graph replay (deg/base must be zero at entry)
        if (lane == 0) g_deg[node] = 0;
        if (node == 0 && lane == 1) g_base = 0;
    }
}

// ---------------- launcher ---------------------------------------------------
extern "C" void kernel_launch(void* const* d_in, const int* in_sizes, int n_in,
                              void* d_out, int out_size) {
    const float* x  = (const float*)d_in[0];
    const int*   ei = (const int*)d_in[1];
    const float* W1 = (const float*)d_in[2];
    const float* b1 = (const float*)d_in[3];
    const float* W2 = (const float*)d_in[4];
    const float* b2 = (const float*)d_in[5];
    const float* W3 = (const float*)d_in[6];
    const float* b3 = (const float*)d_in[7];
    float* out = (float*)d_out;

    int n = in_sizes[0] / CIN;
    int E = in_sizes[1] / 2;
    if (n > NMAX) n = NMAX;
    if (E > EMAX) E = EMAX;
    int nb = (n + 1023) / 1024;
    int eb4 = ((E + 3) / 4 + 255) / 256;

    static cudaStream_t s2 = nullptr;
    static cudaEvent_t evFork = nullptr, evJoin = nullptr;
    if (!s2) {
        cudaStreamCreate(&s2);
        cudaEventCreateWithFlags(&evFork, cudaEventDisableTiming);
        cudaEventCreateWithFlags(&evJoin, cudaEventDisableTiming);
    }

    // fork: prep chain on s2, GEMM1 on main stream
    cudaEventRecord(evFork, 0);
    cudaStreamWaitEvent(s2, evFork, 0);

    k_count<<<eb4, 256, 0, s2>>>(ei, E);
    k_scan<<<nb, 256, 0, s2>>>(n);
    k_fill_csr<<<eb4, 256, 0, s2>>>(ei, E);
    cudaEventRecord(evJoin, s2);

    // layer 1 GEMM: x[128] -> 64 (independent of CSR prep; overlapped)
    k_gemm1<<<592, 128>>>(x, W1, n);

    cudaStreamWaitEvent(0, evJoin, 0);

    int agg_grid = (n + 7) / 8;   // one warp per node, 8 warps/block

    k_agg<64, false><<<agg_grid, 256>>>(b1, nullptr, n);   // + relu
    k_gemm_h<64, 64><<<1184, 128>>>(W2, n);
    k_agg<64, false><<<agg_grid, 256>>>(b2, nullptr, n);   // + relu
    k_gemm_h<64, 40><<<1184, 80>>>(W3, n);
    k_agg<40, true><<<agg_grid, 256>>>(b3, out, n);
}

// round 12
// speedup vs baseline: 1.0683x; 1.0683x over previous
#include <cuda_runtime.h>
#include <cuda_fp16.h>

#define NMAX 100000
#define EMAX 1600000
#define CIN  128

// ---------------- scratch (device globals; no allocation allowed) ----------
// g_deg holds IN-degree (no self loop); zero at entry of every call
// (zero-initialized at load; self-cleaned by final agg each call).
__device__ int   g_deg[NMAX];
__device__ int   g_offs[NMAX];         // CSR start (block-atomic bases; end = start+indeg)
__device__ int   g_cursor[NMAX];
__device__ int   g_base;               // atomic base for block scan (self-cleaned)
__device__ __align__(16) int2   g_csr[EMAX];        // {src, float bits of dinv[src]}
__device__ __align__(16) __half g_h[NMAX * 64];     // gemm output, fp16 (layer3 pitch 40)
__device__ __align__(16) __half g_out_h[NMAX * 64]; // agg output, fp16, RELU APPLIED

// ---------------- prep -------------------------------------------------------
// 4 edges per thread for MLP on the atomic chain.
__global__ void k_count(const int* __restrict__ ei, int E) {
    int i = blockIdx.x * blockDim.x + threadIdx.x;
    int e4 = i * 4;
    if (e4 >= E) return;
    if (e4 + 4 <= E) {
        int4 d = *(const int4*)&ei[E + e4];
        atomicAdd(&g_deg[d.x], 1);
        atomicAdd(&g_deg[d.y], 1);
        atomicAdd(&g_deg[d.z], 1);
        atomicAdd(&g_deg[d.w], 1);
    } else {
        for (int e = e4; e < E; e++) atomicAdd(&g_deg[ei[E + e]], 1);
    }
}

// single-kernel scan of in-degree: block-local scan + atomic base.
__global__ void k_scan(int n) {
    __shared__ int wsum[8];
    __shared__ int sbase;
    int t = threadIdx.x;
    int lane = t & 31, wid = t >> 5;
    int base = blockIdx.x * 1024;
    int loc[4];
    int v = 0;
    #pragma unroll
    for (int j = 0; j < 4; j++) {
        int i = base + t * 4 + j;
        loc[j] = (i < n) ? g_deg[i] : 0;
        v += loc[j];
    }
    int s = v;
    #pragma unroll
    for (int off = 1; off < 32; off <<= 1) {
        int y = __shfl_up_sync(0xffffffffu, s, off);
        if (lane >= off) s += y;
    }
    if (lane == 31) wsum[wid] = s;
    __syncthreads();
    if (t == 0) {
        int acc = 0;
        #pragma unroll
        for (int w = 0; w < 8; w++) { int x2 = wsum[w]; wsum[w] = acc; acc += x2; }
        sbase = atomicAdd(&g_base, acc);
    }
    __syncthreads();
    int run = sbase + wsum[wid] + s - v;
    #pragma unroll
    for (int j = 0; j < 4; j++) {
        int i = base + t * 4 + j;
        if (i < n) {
            g_offs[i] = run;
            g_cursor[i] = run;
            run += loc[j];
        }
    }
}

// CSR fill: {src, dinv[src]}; 4 edges/thread for MLP.
__global__ void k_fill_csr(const int* __restrict__ ei, int E) {
    int i = blockIdx.x * blockDim.x + threadIdx.x;
    int e4 = i * 4;
    if (e4 >= E) return;
    if (e4 + 4 <= E) {
        int4 sv = *(const int4*)&ei[e4];
        int4 dv = *(const int4*)&ei[E + e4];
        float i0 = rsqrtf((float)(g_deg[sv.x] + 1));
        float i1 = rsqrtf((float)(g_deg[sv.y] + 1));
        float i2 = rsqrtf((float)(g_deg[sv.z] + 1));
        float i3 = rsqrtf((float)(g_deg[sv.w] + 1));
        int p0 = atomicAdd(&g_cursor[dv.x], 1);
        int p1 = atomicAdd(&g_cursor[dv.y], 1);
        int p2 = atomicAdd(&g_cursor[dv.z], 1);
        int p3 = atomicAdd(&g_cursor[dv.w], 1);
        g_csr[p0] = make_int2(sv.x, __float_as_int(i0));
        g_csr[p1] = make_int2(sv.y, __float_as_int(i1));
        g_csr[p2] = make_int2(sv.z, __float_as_int(i2));
        g_csr[p3] = make_int2(sv.w, __float_as_int(i3));
    } else {
        for (int e = e4; e < E; e++) {
            int s = ei[e];
            int d = ei[E + e];
            float ds = rsqrtf((float)(g_deg[s] + 1));
            int pos = atomicAdd(&g_cursor[d], 1);
            g_csr[pos] = make_int2(s, __float_as_int(ds));
        }
    }
}

// ---------------- layer-1 GEMM (fp32 SIMT persistent, BM=64, 256 thr) -------
// g_h(fp16) = x(fp32) @ W1
__global__ __launch_bounds__(256)
void k_gemm1(const float* __restrict__ X, const float* __restrict__ W, int n) {
    constexpr int K = 128, COUT = 64, BM = 64;
    constexpr int NT = COUT / 4;             // 16
    constexpr int NTHREADS = 256;            // MT = 16
    __shared__ float ws[K][COUT];
    __shared__ float xs[BM][K];

    int t = threadIdx.x;
    constexpr int WF4 = K * COUT / 4;
    float* wsf = &ws[0][0];
    for (int idx = t; idx < WF4; idx += NTHREADS)
        *(float4*)&wsf[idx * 4] = *(const float4*)&W[idx * 4];

    int nidx = t % NT;
    int midx = t / NT;                       // 0..15
    int ntiles = (n + BM - 1) / BM;

    for (int tile = blockIdx.x; tile < ntiles; tile += gridDim.x) {
        int base = tile * BM;
        __syncthreads();
        constexpr int XF4 = BM * K / 4;
        for (int idx = t; idx < XF4; idx += NTHREADS) {
            int r = idx / (K / 4), kc = idx % (K / 4);
            int gr = base + r;
            float4 v = make_float4(0.f, 0.f, 0.f, 0.f);
            if (gr < n) v = *(const float4*)&X[(size_t)gr * K + kc * 4];
            *(float4*)&xs[r][kc * 4] = v;
        }
        __syncthreads();

        float acc[4][4] = {};
        #pragma unroll 8
        for (int k = 0; k < K; k++) {
            float4 b4 = *(const float4*)&ws[k][nidx * 4];
            float a0 = xs[midx * 4 + 0][k];
            float a1 = xs[midx * 4 + 1][k];
            float a2 = xs[midx * 4 + 2][k];
            float a3 = xs[midx * 4 + 3][k];
            acc[0][0] += a0 * b4.x; acc[0][1] += a0 * b4.y; acc[0][2] += a0 * b4.z; acc[0][3] += a0 * b4.w;
            acc[1][0] += a1 * b4.x; acc[1][1] += a1 * b4.y; acc[1][2] += a1 * b4.z; acc[1][3] += a1 * b4.w;
            acc[2][0] += a2 * b4.x; acc[2][1] += a2 * b4.y; acc[2][2] += a2 * b4.z; acc[2][3] += a2 * b4.w;
            acc[3][0] += a3 * b4.x; acc[3][1] += a3 * b4.y; acc[3][2] += a3 * b4.z; acc[3][3] += a3 * b4.w;
        }

        #pragma unroll
        for (int i = 0; i < 4; i++) {
            int gr = base + midx * 4 + i;
            if (gr < n) {
                __half2 p0 = __floats2half2_rn(acc[i][0], acc[i][1]);
                __half2 p1 = __floats2half2_rn(acc[i][2], acc[i][3]);
                uint2 u = make_uint2(*(unsigned*)&p0, *(unsigned*)&p1);
                *(uint2*)&g_h[(size_t)gr * COUT + nidx * 4] = u;
            }
        }
    }
}

// ---------------- layers 2/3 GEMM (SIMT persistent, fp16 in/out, BM=64) -----
// g_h(fp16) = g_out_h(fp16, relu'd) @ W(fp32)
template <int K, int COUT>
__global__ void k_gemm_h(const float* __restrict__ W, int n) {
    constexpr int BM = 64;
    constexpr int NT = COUT / 4;             // 16 or 10
    constexpr int MT = BM / 4;               // 16
    constexpr int NTHREADS = NT * MT;        // 256 or 160
    __shared__ float ws[K][COUT];
    __shared__ float xs[BM][K];

    int t = threadIdx.x;
    constexpr int WF4 = K * COUT / 4;
    float* wsf = &ws[0][0];
    for (int idx = t; idx < WF4; idx += NTHREADS)
        *(float4*)&wsf[idx * 4] = *(const float4*)&W[idx * 4];

    int nidx = t % NT;
    int midx = t / NT;
    int ntiles = (n + BM - 1) / BM;

    for (int tile = blockIdx.x; tile < ntiles; tile += gridDim.x) {
        int base = tile * BM;
        __syncthreads();
        constexpr int XF4 = BM * K / 4;
        for (int idx = t; idx < XF4; idx += NTHREADS) {
            int r = idx / (K / 4), kc = idx % (K / 4);
            int gr = base + r;
            float4 v = make_float4(0.f, 0.f, 0.f, 0.f);
            if (gr < n) {
                uint2 u = *(const uint2*)&g_out_h[(size_t)gr * K + kc * 4];
                float2 f01 = __half22float2(*(__half2*)&u.x);
                float2 f23 = __half22float2(*(__half2*)&u.y);
                v = make_float4(f01.x, f01.y, f23.x, f23.y);
            }
            *(float4*)&xs[r][kc * 4] = v;
        }
        __syncthreads();

        float acc[4][4] = {};
        #pragma unroll 8
        for (int k = 0; k < K; k++) {
            float4 b4 = *(const float4*)&ws[k][nidx * 4];
            float a0 = xs[midx * 4 + 0][k];
            float a1 = xs[midx * 4 + 1][k];
            float a2 = xs[midx * 4 + 2][k];
            float a3 = xs[midx * 4 + 3][k];
            acc[0][0] += a0 * b4.x; acc[0][1] += a0 * b4.y; acc[0][2] += a0 * b4.z; acc[0][3] += a0 * b4.w;
            acc[1][0] += a1 * b4.x; acc[1][1] += a1 * b4.y; acc[1][2] += a1 * b4.z; acc[1][3] += a1 * b4.w;
            acc[2][0] += a2 * b4.x; acc[2][1] += a2 * b4.y; acc[2][2] += a2 * b4.z; acc[2][3] += a2 * b4.w;
            acc[3][0] += a3 * b4.x; acc[3][1] += a3 * b4.y; acc[3][2] += a3 * b4.z; acc[3][3] += a3 * b4.w;
        }

        #pragma unroll
        for (int i = 0; i < 4; i++) {
            int gr = base + midx * 4 + i;
            if (gr < n) {
                __half2 p0 = __floats2half2_rn(acc[i][0], acc[i][1]);
                __half2 p1 = __floats2half2_rn(acc[i][2], acc[i][3]);
                uint2 u = make_uint2(*(unsigned*)&p0, *(unsigned*)&p1);
                *(uint2*)&g_h[(size_t)gr * COUT + nidx * 4] = u;
            }
        }
    }
}

// ---------------- aggregation ------------------------------------------------
// out = b + dinv_d * (dinv_d*h[node] + sum_s dinv_s*h[s])
// one warp per node; lane owns 2 channels; edge record broadcast-loaded;
// unroll 4. FINAL: fp32 OUT arg + self-clean g_deg/g_base; else relu->fp16.
template <int C, bool FINAL>
__global__ void k_agg(const float* __restrict__ b, float* __restrict__ OUTarg,
                      int n) {
    const __half* H = (const __half*)g_h;

    int node = (blockIdx.x * blockDim.x + threadIdx.x) >> 5;
    int lane = threadIdx.x & 31;
    if (node >= n) return;
    int c = lane * 2;
    bool act = (c < C);

    int indeg = g_deg[node];
    float dinv = rsqrtf((float)(indeg + 1));

    float2 acc = make_float2(0.f, 0.f);
    if (act) {
        float2 hv = __half22float2(*(const __half2*)&H[(size_t)node * C + c]);
        acc.x = dinv * hv.x;
        acc.y = dinv * hv.y;
    }

    int e0 = g_offs[node];
    int e1 = e0 + indeg;
    int e = e0;
    for (; e + 4 <= e1; e += 4) {
        int2 r0 = g_csr[e];
        int2 r1 = g_csr[e + 1];
        int2 r2 = g_csr[e + 2];
        int2 r3 = g_csr[e + 3];
        if (act) {
            float2 h0 = __half22float2(*(const __half2*)&H[(size_t)r0.x * C + c]);
            float2 h1 = __half22float2(*(const __half2*)&H[(size_t)r1.x * C + c]);
            float2 h2 = __half22float2(*(const __half2*)&H[(size_t)r2.x * C + c]);
            float2 h3 = __half22float2(*(const __half2*)&H[(size_t)r3.x * C + c]);
            float n0 = __int_as_float(r0.y), n1 = __int_as_float(r1.y);
            float n2 = __int_as_float(r2.y), n3 = __int_as_float(r3.y);
            acc.x += n0 * h0.x; acc.y += n0 * h0.y;
            acc.x += n1 * h1.x; acc.y += n1 * h1.y;
            acc.x += n2 * h2.x; acc.y += n2 * h2.y;
            acc.x += n3 * h3.x; acc.y += n3 * h3.y;
        }
    }
    for (; e < e1; e++) {
        int2 r = g_csr[e];
        if (act) {
            float2 hv = __half22float2(*(const __half2*)&H[(size_t)r.x * C + c]);
            float nn = __int_as_float(r.y);
            acc.x += nn * hv.x; acc.y += nn * hv.y;
        }
    }
    if (act) {
        float ox = b[c]     + dinv * acc.x;
        float oy = b[c + 1] + dinv * acc.y;
        if (FINAL) {
            *(float2*)&OUTarg[(size_t)node * C + c] = make_float2(ox, oy);
        } else {
            ox = fmaxf(ox, 0.f);
            oy = fmaxf(oy, 0.f);
            __half2 p = __floats2half2_rn(ox, oy);
            *(unsigned*)&g_out_h[(size_t)node * C + c] = *(unsigned*)&p;
        }
    }
    if (FINAL) {
        // self-clean for next graph replay (deg/base must be zero at entry)
        if (lane == 0) g_deg[node] = 0;
        if (node == 0 && lane == 1) g_base = 0;
    }
}

// ---------------- launcher ---------------------------------------------------
extern "C" void kernel_launch(void* const* d_in, const int* in_sizes, int n_in,
                              void* d_out, int out_size) {
    const float* x  = (const float*)d_in[0];
    const int*   ei = (const int*)d_in[1];
    const float* W1 = (const float*)d_in[2];
    const float* b1 = (const float*)d_in[3];
    const float* W2 = (const float*)d_in[4];
    const float* b2 = (const float*)d_in[5];
    const float* W3 = (const float*)d_in[6];
    const float* b3 = (const float*)d_in[7];
    float* out = (float*)d_out;

    int n = in_sizes[0] / CIN;
    int E = in_sizes[1] / 2;
    if (n > NMAX) n = NMAX;
    if (E > EMAX) E = EMAX;
    int nb = (n + 1023) / 1024;
    int eb4 = ((E + 3) / 4 + 255) / 256;

    static cudaStream_t s2 = nullptr;
    static cudaEvent_t evFork = nullptr, evJoin = nullptr;
    if (!s2) {
        cudaStreamCreate(&s2);
        cudaEventCreateWithFlags(&evFork, cudaEventDisableTiming);
        cudaEventCreateWithFlags(&evJoin, cudaEventDisableTiming);
    }

    // fork: prep chain on s2, GEMM1 on main stream
    cudaEventRecord(evFork, 0);
    cudaStreamWaitEvent(s2, evFork, 0);

    k_count<<<eb4, 256, 0, s2>>>(ei, E);
    k_scan<<<nb, 256, 0, s2>>>(n);
    k_fill_csr<<<eb4, 256, 0, s2>>>(ei, E);
    cudaEventRecord(evJoin, s2);

    // layer 1 GEMM: x[128] -> 64 (independent of CSR prep; overlapped)
    k_gemm1<<<444, 256>>>(x, W1, n);

    cudaStreamWaitEvent(0, evJoin, 0);

    int agg_grid = (n + 7) / 8;   // one warp per node, 8 warps/block

    k_agg<64, false><<<agg_grid, 256>>>(b1, nullptr, n);   // + relu
    k_gemm_h<64, 64><<<592, 256>>>(W2, n);
    k_agg<64, false><<<agg_grid, 256>>>(b2, nullptr, n);   // + relu
    k_gemm_h<64, 40><<<592, 160>>>(W3, n);
    k_agg<40, true><<<agg_grid, 256>>>(b3, out, n);
}

// round 13
// speedup vs baseline: 1.0758x; 1.0070x over previous
#include <cuda_runtime.h>
#include <cuda_fp16.h>

#define NMAX 100000
#define EMAX 1600000
#define CIN  128

// ---------------- scratch (device globals; no allocation allowed) ----------
// g_deg holds IN-degree (no self loop); zero at entry of every call
// (zero-initialized at load; self-cleaned by final agg each call).
__device__ int   g_deg[NMAX];
__device__ int   g_offs[NMAX];         // CSR start (block-atomic bases; end = start+indeg)
__device__ int   g_cursor[NMAX];
__device__ int   g_base;               // atomic base for block scan (self-cleaned)
__device__ __align__(16) int2   g_csr[EMAX];        // {src, float bits of dinv[src]}
__device__ __align__(16) __half g_h[NMAX * 64];     // gemm output, fp16 (layer3 pitch 40)
__device__ __align__(16) __half g_out_h[NMAX * 64]; // agg output, fp16, RELU APPLIED

// ---------------- prep -------------------------------------------------------
__global__ void k_count(const int* __restrict__ ei, int E) {
    int i = blockIdx.x * blockDim.x + threadIdx.x;
    int e4 = i * 4;
    if (e4 >= E) return;
    if (e4 + 4 <= E) {
        int4 d = *(const int4*)&ei[E + e4];
        atomicAdd(&g_deg[d.x], 1);
        atomicAdd(&g_deg[d.y], 1);
        atomicAdd(&g_deg[d.z], 1);
        atomicAdd(&g_deg[d.w], 1);
    } else {
        for (int e = e4; e < E; e++) atomicAdd(&g_deg[ei[E + e]], 1);
    }
}

__global__ void k_scan(int n) {
    __shared__ int wsum[8];
    __shared__ int sbase;
    int t = threadIdx.x;
    int lane = t & 31, wid = t >> 5;
    int base = blockIdx.x * 1024;
    int loc[4];
    int v = 0;
    #pragma unroll
    for (int j = 0; j < 4; j++) {
        int i = base + t * 4 + j;
        loc[j] = (i < n) ? g_deg[i] : 0;
        v += loc[j];
    }
    int s = v;
    #pragma unroll
    for (int off = 1; off < 32; off <<= 1) {
        int y = __shfl_up_sync(0xffffffffu, s, off);
        if (lane >= off) s += y;
    }
    if (lane == 31) wsum[wid] = s;
    __syncthreads();
    if (t == 0) {
        int acc = 0;
        #pragma unroll
        for (int w = 0; w < 8; w++) { int x2 = wsum[w]; wsum[w] = acc; acc += x2; }
        sbase = atomicAdd(&g_base, acc);
    }
    __syncthreads();
    int run = sbase + wsum[wid] + s - v;
    #pragma unroll
    for (int j = 0; j < 4; j++) {
        int i = base + t * 4 + j;
        if (i < n) {
            g_offs[i] = run;
            g_cursor[i] = run;
            run += loc[j];
        }
    }
}

__global__ void k_fill_csr(const int* __restrict__ ei, int E) {
    int i = blockIdx.x * blockDim.x + threadIdx.x;
    int e4 = i * 4;
    if (e4 >= E) return;
    if (e4 + 4 <= E) {
        int4 sv = *(const int4*)&ei[e4];
        int4 dv = *(const int4*)&ei[E + e4];
        float i0 = rsqrtf((float)(g_deg[sv.x] + 1));
        float i1 = rsqrtf((float)(g_deg[sv.y] + 1));
        float i2 = rsqrtf((float)(g_deg[sv.z] + 1));
        float i3 = rsqrtf((float)(g_deg[sv.w] + 1));
        int p0 = atomicAdd(&g_cursor[dv.x], 1);
        int p1 = atomicAdd(&g_cursor[dv.y], 1);
        int p2 = atomicAdd(&g_cursor[dv.z], 1);
        int p3 = atomicAdd(&g_cursor[dv.w], 1);
        g_csr[p0] = make_int2(sv.x, __float_as_int(i0));
        g_csr[p1] = make_int2(sv.y, __float_as_int(i1));
        g_csr[p2] = make_int2(sv.z, __float_as_int(i2));
        g_csr[p3] = make_int2(sv.w, __float_as_int(i3));
    } else {
        for (int e = e4; e < E; e++) {
            int s = ei[e];
            int d = ei[E + e];
            float ds = rsqrtf((float)(g_deg[s] + 1));
            int pos = atomicAdd(&g_cursor[d], 1);
            g_csr[pos] = make_int2(s, __float_as_int(ds));
        }
    }
}

// ---------------- layer-1 GEMM (fp32 SIMT persistent, BM=64, 256 thr) -------
__global__ __launch_bounds__(256)
void k_gemm1(const float* __restrict__ X, const float* __restrict__ W, int n) {
    constexpr int K = 128, COUT = 64, BM = 64;
    constexpr int NT = COUT / 4;             // 16
    constexpr int NTHREADS = 256;
    __shared__ float ws[K][COUT];
    __shared__ float xs[BM][K];

    int t = threadIdx.x;
    constexpr int WF4 = K * COUT / 4;
    float* wsf = &ws[0][0];
    for (int idx = t; idx < WF4; idx += NTHREADS)
        *(float4*)&wsf[idx * 4] = *(const float4*)&W[idx * 4];

    int nidx = t % NT;
    int midx = t / NT;
    int ntiles = (n + BM - 1) / BM;

    for (int tile = blockIdx.x; tile < ntiles; tile += gridDim.x) {
        int base = tile * BM;
        __syncthreads();
        constexpr int XF4 = BM * K / 4;
        for (int idx = t; idx < XF4; idx += NTHREADS) {
            int r = idx / (K / 4), kc = idx % (K / 4);
            int gr = base + r;
            float4 v = make_float4(0.f, 0.f, 0.f, 0.f);
            if (gr < n) v = *(const float4*)&X[(size_t)gr * K + kc * 4];
            *(float4*)&xs[r][kc * 4] = v;
        }
        __syncthreads();

        float acc[4][4] = {};
        #pragma unroll 8
        for (int k = 0; k < K; k++) {
            float4 b4 = *(const float4*)&ws[k][nidx * 4];
            float a0 = xs[midx * 4 + 0][k];
            float a1 = xs[midx * 4 + 1][k];
            float a2 = xs[midx * 4 + 2][k];
            float a3 = xs[midx * 4 + 3][k];
            acc[0][0] += a0 * b4.x; acc[0][1] += a0 * b4.y; acc[0][2] += a0 * b4.z; acc[0][3] += a0 * b4.w;
            acc[1][0] += a1 * b4.x; acc[1][1] += a1 * b4.y; acc[1][2] += a1 * b4.z; acc[1][3] += a1 * b4.w;
            acc[2][0] += a2 * b4.x; acc[2][1] += a2 * b4.y; acc[2][2] += a2 * b4.z; acc[2][3] += a2 * b4.w;
            acc[3][0] += a3 * b4.x; acc[3][1] += a3 * b4.y; acc[3][2] += a3 * b4.z; acc[3][3] += a3 * b4.w;
        }

        #pragma unroll
        for (int i = 0; i < 4; i++) {
            int gr = base + midx * 4 + i;
            if (gr < n) {
                __half2 p0 = __floats2half2_rn(acc[i][0], acc[i][1]);
                __half2 p1 = __floats2half2_rn(acc[i][2], acc[i][3]);
                uint2 u = make_uint2(*(unsigned*)&p0, *(unsigned*)&p1);
                *(uint2*)&g_h[(size_t)gr * COUT + nidx * 4] = u;
            }
        }
    }
}

// ---------------- layers 2/3 GEMM (SIMT persistent, fp16 in/out, BM=64) -----
template <int K, int COUT>
__global__ void k_gemm_h(const float* __restrict__ W, int n) {
    constexpr int BM = 64;
    constexpr int NT = COUT / 4;
    constexpr int MT = BM / 4;
    constexpr int NTHREADS = NT * MT;
    __shared__ float ws[K][COUT];
    __shared__ float xs[BM][K];

    int t = threadIdx.x;
    constexpr int WF4 = K * COUT / 4;
    float* wsf = &ws[0][0];
    for (int idx = t; idx < WF4; idx += NTHREADS)
        *(float4*)&wsf[idx * 4] = *(const float4*)&W[idx * 4];

    int nidx = t % NT;
    int midx = t / NT;
    int ntiles = (n + BM - 1) / BM;

    for (int tile = blockIdx.x; tile < ntiles; tile += gridDim.x) {
        int base = tile * BM;
        __syncthreads();
        constexpr int XF4 = BM * K / 4;
        for (int idx = t; idx < XF4; idx += NTHREADS) {
            int r = idx / (K / 4), kc = idx % (K / 4);
            int gr = base + r;
            float4 v = make_float4(0.f, 0.f, 0.f, 0.f);
            if (gr < n) {
                uint2 u = *(const uint2*)&g_out_h[(size_t)gr * K + kc * 4];
                float2 f01 = __half22float2(*(__half2*)&u.x);
                float2 f23 = __half22float2(*(__half2*)&u.y);
                v = make_float4(f01.x, f01.y, f23.x, f23.y);
            }
            *(float4*)&xs[r][kc * 4] = v;
        }
        __syncthreads();

        float acc[4][4] = {};
        #pragma unroll 8
        for (int k = 0; k < K; k++) {
            float4 b4 = *(const float4*)&ws[k][nidx * 4];
            float a0 = xs[midx * 4 + 0][k];
            float a1 = xs[midx * 4 + 1][k];
            float a2 = xs[midx * 4 + 2][k];
            float a3 = xs[midx * 4 + 3][k];
            acc[0][0] += a0 * b4.x; acc[0][1] += a0 * b4.y; acc[0][2] += a0 * b4.z; acc[0][3] += a0 * b4.w;
            acc[1][0] += a1 * b4.x; acc[1][1] += a1 * b4.y; acc[1][2] += a1 * b4.z; acc[1][3] += a1 * b4.w;
            acc[2][0] += a2 * b4.x; acc[2][1] += a2 * b4.y; acc[2][2] += a2 * b4.z; acc[2][3] += a2 * b4.w;
            acc[3][0] += a3 * b4.x; acc[3][1] += a3 * b4.y; acc[3][2] += a3 * b4.z; acc[3][3] += a3 * b4.w;
        }

        #pragma unroll
        for (int i = 0; i < 4; i++) {
            int gr = base + midx * 4 + i;
            if (gr < n) {
                __half2 p0 = __floats2half2_rn(acc[i][0], acc[i][1]);
                __half2 p1 = __floats2half2_rn(acc[i][2], acc[i][3]);
                uint2 u = make_uint2(*(unsigned*)&p0, *(unsigned*)&p1);
                *(uint2*)&g_h[(size_t)gr * COUT + nidx * 4] = u;
            }
        }
    }
}

// ---------------- aggregation C=64 (layers 1/2), half-warp split -------------
// Lanes 0-15 process even edges, 16-31 odd edges; lane owns 4 channels.
// One gather LDG serves 2 edges. shfl_xor(16) combines halves at the end.
// Writes relu(out) fp16 to g_out_h.
__global__ void k_agg64(const float* __restrict__ b, int n) {
    const __half* H = (const __half*)g_h;

    int node = (blockIdx.x * blockDim.x + threadIdx.x) >> 5;
    int lane = threadIdx.x & 31;
    if (node >= n) return;
    int half = lane >> 4;      // 0 or 1
    int c = (lane & 15) * 4;   // channel base, 0..60

    int indeg = g_deg[node];
    float dinv = rsqrtf((float)(indeg + 1));

    // self term: half 0 contributes dinv * h[node]
    float a0, a1, a2, a3;
    {
        uint2 u = *(const uint2*)&H[(size_t)node * 64 + c];
        float2 f01 = __half22float2(*(__half2*)&u.x);
        float2 f23 = __half22float2(*(__half2*)&u.y);
        float w0 = half ? 0.f : dinv;
        a0 = w0 * f01.x; a1 = w0 * f01.y; a2 = w0 * f23.x; a3 = w0 * f23.y;
    }

    int e0 = g_offs[node];
    int e1 = e0 + indeg;
    int e = e0;
    // 8 edges per iteration: 4 csr LDG + 4 gather LDG per warp
    for (; e + 8 <= e1; e += 8) {
        #pragma unroll
        for (int j = 0; j < 4; j++) {
            int2 r = g_csr[e + j * 2 + half];
            float nr = __int_as_float(r.y);
            uint2 u = *(const uint2*)&H[(size_t)r.x * 64 + c];
            float2 g01 = __half22float2(*(__half2*)&u.x);
            float2 g23 = __half22float2(*(__half2*)&u.y);
            a0 += nr * g01.x; a1 += nr * g01.y;
            a2 += nr * g23.x; a3 += nr * g23.y;
        }
    }
    for (; e < e1; e += 2) {
        int idx = e + half;
        int2 r = (idx < e1) ? g_csr[idx] : make_int2(node, 0);
        float nr = __int_as_float(r.y);
        uint2 u = *(const uint2*)&H[(size_t)r.x * 64 + c];
        float2 g01 = __half22float2(*(__half2*)&u.x);
        float2 g23 = __half22float2(*(__half2*)&u.y);
        a0 += nr * g01.x; a1 += nr * g01.y;
        a2 += nr * g23.x; a3 += nr * g23.y;
    }

    // combine halves
    a0 += __shfl_xor_sync(0xffffffffu, a0, 16);
    a1 += __shfl_xor_sync(0xffffffffu, a1, 16);
    a2 += __shfl_xor_sync(0xffffffffu, a2, 16);
    a3 += __shfl_xor_sync(0xffffffffu, a3, 16);

    if (half == 0) {
        float o0 = fmaxf(b[c]     + dinv * a0, 0.f);
        float o1 = fmaxf(b[c + 1] + dinv * a1, 0.f);
        float o2 = fmaxf(b[c + 2] + dinv * a2, 0.f);
        float o3 = fmaxf(b[c + 3] + dinv * a3, 0.f);
        __half2 p0 = __floats2half2_rn(o0, o1);
        __half2 p1 = __floats2half2_rn(o2, o3);
        uint2 u = make_uint2(*(unsigned*)&p0, *(unsigned*)&p1);
        *(uint2*)&g_out_h[(size_t)node * 64 + c] = u;
    }
}

// ---------------- final aggregation (C=40, fp32 out, self-clean) -------------
__global__ void k_agg_final(const float* __restrict__ b, float* __restrict__ OUT,
                            int n) {
    constexpr int C = 40;
    const __half* H = (const __half*)g_h;

    int node = (blockIdx.x * blockDim.x + threadIdx.x) >> 5;
    int lane = threadIdx.x & 31;
    if (node >= n) return;
    int c = lane * 2;
    bool act = (c < C);

    int indeg = g_deg[node];
    float dinv = rsqrtf((float)(indeg + 1));

    float2 acc = make_float2(0.f, 0.f);
    if (act) {
        float2 hv = __half22float2(*(const __half2*)&H[(size_t)node * C + c]);
        acc.x = dinv * hv.x;
        acc.y = dinv * hv.y;
    }

    int e0 = g_offs[node];
    int e1 = e0 + indeg;
    int e = e0;
    for (; e + 4 <= e1; e += 4) {
        int2 r0 = g_csr[e];
        int2 r1 = g_csr[e + 1];
        int2 r2 = g_csr[e + 2];
        int2 r3 = g_csr[e + 3];
        if (act) {
            float2 h0 = __half22float2(*(const __half2*)&H[(size_t)r0.x * C + c]);
            float2 h1 = __half22float2(*(const __half2*)&H[(size_t)r1.x * C + c]);
            float2 h2 = __half22float2(*(const __half2*)&H[(size_t)r2.x * C + c]);
            float2 h3 = __half22float2(*(const __half2*)&H[(size_t)r3.x * C + c]);
            float n0 = __int_as_float(r0.y), n1 = __int_as_float(r1.y);
            float n2 = __int_as_float(r2.y), n3 = __int_as_float(r3.y);
            acc.x += n0 * h0.x; acc.y += n0 * h0.y;
            acc.x += n1 * h1.x; acc.y += n1 * h1.y;
            acc.x += n2 * h2.x; acc.y += n2 * h2.y;
            acc.x += n3 * h3.x; acc.y += n3 * h3.y;
        }
    }
    for (; e < e1; e++) {
        int2 r = g_csr[e];
        if (act) {
            float2 hv = __half22float2(*(const __half2*)&H[(size_t)r.x * C + c]);
            float nn = __int_as_float(r.y);
            acc.x += nn * hv.x; acc.y += nn * hv.y;
        }
    }
    if (act) {
        float ox = b[c]     + dinv * acc.x;
        float oy = b[c + 1] + dinv * acc.y;
        *(float2*)&OUT[(size_t)node * C + c] = make_float2(ox, oy);
    }
    // self-clean for next graph replay
    if (lane == 0) g_deg[node] = 0;
    if (node == 0 && lane == 1) g_base = 0;
}

// ---------------- launcher ---------------------------------------------------
extern "C" void kernel_launch(void* const* d_in, const int* in_sizes, int n_in,
                              void* d_out, int out_size) {
    const float* x  = (const float*)d_in[0];
    const int*   ei = (const int*)d_in[1];
    const float* W1 = (const float*)d_in[2];
    const float* b1 = (const float*)d_in[3];
    const float* W2 = (const float*)d_in[4];
    const float* b2 = (const float*)d_in[5];
    const float* W3 = (const float*)d_in[6];
    const float* b3 = (const float*)d_in[7];
    float* out = (float*)d_out;

    int n = in_sizes[0] / CIN;
    int E = in_sizes[1] / 2;
    if (n > NMAX) n = NMAX;
    if (E > EMAX) E = EMAX;
    int nb = (n + 1023) / 1024;
    int eb4 = ((E + 3) / 4 + 255) / 256;

    static cudaStream_t s2 = nullptr;
    static cudaEvent_t evFork = nullptr, evJoin = nullptr;
    if (!s2) {
        cudaStreamCreate(&s2);
        cudaEventCreateWithFlags(&evFork, cudaEventDisableTiming);
        cudaEventCreateWithFlags(&evJoin, cudaEventDisableTiming);
    }

    // fork: prep chain on s2, GEMM1 on main stream
    cudaEventRecord(evFork, 0);
    cudaStreamWaitEvent(s2, evFork, 0);

    k_count<<<eb4, 256, 0, s2>>>(ei, E);
    k_scan<<<nb, 256, 0, s2>>>(n);
    k_fill_csr<<<eb4, 256, 0, s2>>>(ei, E);
    cudaEventRecord(evJoin, s2);

    // layer 1 GEMM: x[128] -> 64 (independent of CSR prep; overlapped)
    k_gemm1<<<444, 256>>>(x, W1, n);

    cudaStreamWaitEvent(0, evJoin, 0);

    int agg_grid = (n + 7) / 8;   // one warp per node, 8 warps/block

    k_agg64<<<agg_grid, 256>>>(b1, n);                 // + relu
    k_gemm_h<64, 64><<<592, 256>>>(W2, n);
    k_agg64<<<agg_grid, 256>>>(b2, n);                 // + relu
    k_gemm_h<64, 40><<<592, 160>>>(W3, n);
    k_agg_final<<<agg_grid, 256>>>(b3, out, n);
}

// round 15
// speedup vs baseline: 1.0825x; 1.0062x over previous
#include <cuda_runtime.h>
#include <cuda_fp16.h>

#define NMAX 100000
#define EMAX 1600000
#define CIN  128

// ---------------- scratch (device globals; no allocation allowed) ----------
__device__ int   g_deg[NMAX];          // IN-degree; zero at entry (self-cleaned)
__device__ int   g_offs[NMAX];
__device__ int   g_cursor[NMAX];
__device__ int   g_base;
__device__ __align__(16) int2   g_csr[EMAX];        // {src, float bits of dinv[src]}
__device__ __align__(16) __half g_h[NMAX * 64];     // gemm output, fp16
__device__ __align__(16) __half g_out_h[NMAX * 64]; // agg output, fp16, RELU'd

// ---------------- prep -------------------------------------------------------
__global__ void k_count(const int* __restrict__ ei, int E) {
    int i = blockIdx.x * blockDim.x + threadIdx.x;
    int e4 = i * 4;
    if (e4 >= E) return;
    if (e4 + 4 <= E) {
        int4 d = *(const int4*)&ei[E + e4];
        atomicAdd(&g_deg[d.x], 1);
        atomicAdd(&g_deg[d.y], 1);
        atomicAdd(&g_deg[d.z], 1);
        atomicAdd(&g_deg[d.w], 1);
    } else {
        for (int e = e4; e < E; e++) atomicAdd(&g_deg[ei[E + e]], 1);
    }
}

__global__ void k_scan(int n) {
    __shared__ int wsum[8];
    __shared__ int sbase;
    int t = threadIdx.x;
    int lane = t & 31, wid = t >> 5;
    int base = blockIdx.x * 1024;
    int loc[4];
    int v = 0;
    #pragma unroll
    for (int j = 0; j < 4; j++) {
        int i = base + t * 4 + j;
        loc[j] = (i < n) ? g_deg[i] : 0;
        v += loc[j];
    }
    int s = v;
    #pragma unroll
    for (int off = 1; off < 32; off <<= 1) {
        int y = __shfl_up_sync(0xffffffffu, s, off);
        if (lane >= off) s += y;
    }
    if (lane == 31) wsum[wid] = s;
    __syncthreads();
    if (t == 0) {
        int acc = 0;
        #pragma unroll
        for (int w = 0; w < 8; w++) { int x2 = wsum[w]; wsum[w] = acc; acc += x2; }
        sbase = atomicAdd(&g_base, acc);
    }
    __syncthreads();
    int run = sbase + wsum[wid] + s - v;
    #pragma unroll
    for (int j = 0; j < 4; j++) {
        int i = base + t * 4 + j;
        if (i < n) {
            g_offs[i] = run;
            g_cursor[i] = run;
            run += loc[j];
        }
    }
}

__global__ void k_fill_csr(const int* __restrict__ ei, int E) {
    int i = blockIdx.x * blockDim.x + threadIdx.x;
    int e4 = i * 4;
    if (e4 >= E) return;
    if (e4 + 4 <= E) {
        int4 sv = *(const int4*)&ei[e4];
        int4 dv = *(const int4*)&ei[E + e4];
        float i0 = rsqrtf((float)(g_deg[sv.x] + 1));
        float i1 = rsqrtf((float)(g_deg[sv.y] + 1));
        float i2 = rsqrtf((float)(g_deg[sv.z] + 1));
        float i3 = rsqrtf((float)(g_deg[sv.w] + 1));
        int p0 = atomicAdd(&g_cursor[dv.x], 1);
        int p1 = atomicAdd(&g_cursor[dv.y], 1);
        int p2 = atomicAdd(&g_cursor[dv.z], 1);
        int p3 = atomicAdd(&g_cursor[dv.w], 1);
        g_csr[p0] = make_int2(sv.x, __float_as_int(i0));
        g_csr[p1] = make_int2(sv.y, __float_as_int(i1));
        g_csr[p2] = make_int2(sv.z, __float_as_int(i2));
        g_csr[p3] = make_int2(sv.w, __float_as_int(i3));
    } else {
        for (int e = e4; e < E; e++) {
            int s = ei[e];
            int d = ei[E + e];
            float ds = rsqrtf((float)(g_deg[s] + 1));
            int pos = atomicAdd(&g_cursor[d], 1);
            g_csr[pos] = make_int2(s, __float_as_int(ds));
        }
    }
}

// ---------------- layer-1 GEMM (BM=64, 256 thr, fp16 X-tile) -----------------
// g_h(fp16) = x(fp32->fp16) @ W1(fp32)
__global__ __launch_bounds__(256, 4)
void k_gemm1(const float* __restrict__ X, const float* __restrict__ W, int n) {
    constexpr int K = 128, COUT = 64, BM = 64;
    constexpr int NT = COUT / 4;             // 16
    constexpr int NTHREADS = 256;
    __shared__ float  ws[K][COUT];           // 32 KB
    __shared__ __half xs[BM][K];             // 16 KB

    int t = threadIdx.x;
    constexpr int WF4 = K * COUT / 4;
    float* wsf = &ws[0][0];
    for (int idx = t; idx < WF4; idx += NTHREADS)
        *(float4*)&wsf[idx * 4] = *(const float4*)&W[idx * 4];

    int nidx = t % NT;
    int midx = t / NT;
    int ntiles = (n + BM - 1) / BM;

    for (int tile = blockIdx.x; tile < ntiles; tile += gridDim.x) {
        int base = tile * BM;
        __syncthreads();
        constexpr int XF4 = BM * K / 4;
        for (int idx = t; idx < XF4; idx += NTHREADS) {
            int r = idx / (K / 4), kc = idx % (K / 4);
            int gr = base + r;
            float4 v = make_float4(0.f, 0.f, 0.f, 0.f);
            if (gr < n) v = *(const float4*)&X[(size_t)gr * K + kc * 4];
            __half2 p0 = __floats2half2_rn(v.x, v.y);
            __half2 p1 = __floats2half2_rn(v.z, v.w);
            *(uint2*)&xs[r][kc * 4] = make_uint2(*(unsigned*)&p0, *(unsigned*)&p1);
        }
        __syncthreads();

        float acc[4][4] = {};
        #pragma unroll 4
        for (int k4 = 0; k4 < K / 4; k4++) {
            uint2 ar[4];
            #pragma unroll
            for (int i = 0; i < 4; i++)
                ar[i] = *(const uint2*)&xs[midx * 4 + i][k4 * 4];
            float a[4][4];
            #pragma unroll
            for (int i = 0; i < 4; i++) {
                float2 f01 = __half22float2(*(__half2*)&ar[i].x);
                float2 f23 = __half22float2(*(__half2*)&ar[i].y);
                a[i][0] = f01.x; a[i][1] = f01.y; a[i][2] = f23.x; a[i][3] = f23.y;
            }
            #pragma unroll
            for (int kk = 0; kk < 4; kk++) {
                float4 b4 = *(const float4*)&ws[k4 * 4 + kk][nidx * 4];
                #pragma unroll
                for (int i = 0; i < 4; i++) {
                    acc[i][0] += a[i][kk] * b4.x;
                    acc[i][1] += a[i][kk] * b4.y;
                    acc[i][2] += a[i][kk] * b4.z;
                    acc[i][3] += a[i][kk] * b4.w;
                }
            }
        }

        #pragma unroll
        for (int i = 0; i < 4; i++) {
            int gr = base + midx * 4 + i;
            if (gr < n) {
                __half2 p0 = __floats2half2_rn(acc[i][0], acc[i][1]);
                __half2 p1 = __floats2half2_rn(acc[i][2], acc[i][3]);
                uint2 u = make_uint2(*(unsigned*)&p0, *(unsigned*)&p1);
                *(uint2*)&g_h[(size_t)gr * COUT + nidx * 4] = u;
            }
        }
    }
}

// ---------------- layers 2/3 GEMM (fp16 X-tile passthrough) ------------------
// g_h(fp16) = g_out_h(fp16, relu'd) @ W(fp32)
template <int K, int COUT>
__global__ void k_gemm_h(const float* __restrict__ W, int n) {
    constexpr int BM = 64;
    constexpr int NT = COUT / 4;
    constexpr int MT = BM / 4;
    constexpr int NTHREADS = NT * MT;
    __shared__ float  ws[K][COUT];
    __shared__ __half xs[BM][K];             // 8 KB

    int t = threadIdx.x;
    constexpr int WF4 = K * COUT / 4;
    float* wsf = &ws[0][0];
    for (int idx = t; idx < WF4; idx += NTHREADS)
        *(float4*)&wsf[idx * 4] = *(const float4*)&W[idx * 4];

    int nidx = t % NT;
    int midx = t / NT;
    int ntiles = (n + BM - 1) / BM;

    for (int tile = blockIdx.x; tile < ntiles; tile += gridDim.x) {
        int base = tile * BM;
        __syncthreads();
        constexpr int XF4 = BM * K / 4;      // 4 halves per idx
        for (int idx = t; idx < XF4; idx += NTHREADS) {
            int r = idx / (K / 4), kc = idx % (K / 4);
            int gr = base + r;
            uint2 u = make_uint2(0u, 0u);
            if (gr < n) u = *(const uint2*)&g_out_h[(size_t)gr * K + kc * 4];
            *(uint2*)&xs[r][kc * 4] = u;
        }
        __syncthreads();

        float acc[4][4] = {};
        #pragma unroll 4
        for (int k4 = 0; k4 < K / 4; k4++) {
            uint2 ar[4];
            #pragma unroll
            for (int i = 0; i < 4; i++)
                ar[i] = *(const uint2*)&xs[midx * 4 + i][k4 * 4];
            float a[4][4];
            #pragma unroll
            for (int i = 0; i < 4; i++) {
                float2 f01 = __half22float2(*(__half2*)&ar[i].x);
                float2 f23 = __half22float2(*(__half2*)&ar[i].y);
                a[i][0] = f01.x; a[i][1] = f01.y; a[i][2] = f23.x; a[i][3] = f23.y;
            }
            #pragma unroll
            for (int kk = 0; kk < 4; kk++) {
                float4 b4 = *(const float4*)&ws[k4 * 4 + kk][nidx * 4];
                #pragma unroll
                for (int i = 0; i < 4; i++) {
                    acc[i][0] += a[i][kk] * b4.x;
                    acc[i][1] += a[i][kk] * b4.y;
                    acc[i][2] += a[i][kk] * b4.z;
                    acc[i][3] += a[i][kk] * b4.w;
                }
            }
        }

        #pragma unroll
        for (int i = 0; i < 4; i++) {
            int gr = base + midx * 4 + i;
            if (gr < n) {
                __half2 p0 = __floats2half2_rn(acc[i][0], acc[i][1]);
                __half2 p1 = __floats2half2_rn(acc[i][2], acc[i][3]);
                uint2 u = make_uint2(*(unsigned*)&p0, *(unsigned*)&p1);
                *(uint2*)&g_h[(size_t)gr * COUT + nidx * 4] = u;
            }
        }
    }
}

// ---------------- aggregation C=64 (layers 1/2), half-warp split -------------
__global__ void k_agg64(const float* __restrict__ b, int n) {
    const __half* H = (const __half*)g_h;

    int node = (blockIdx.x * blockDim.x + threadIdx.x) >> 5;
    int lane = threadIdx.x & 31;
    if (node >= n) return;
    int half = lane >> 4;
    int c = (lane & 15) * 4;

    int indeg = g_deg[node];
    float dinv = rsqrtf((float)(indeg + 1));

    float a0, a1, a2, a3;
    {
        uint2 u = *(const uint2*)&H[(size_t)node * 64 + c];
        float2 f01 = __half22float2(*(__half2*)&u.x);
        float2 f23 = __half22float2(*(__half2*)&u.y);
        float w0 = half ? 0.f : dinv;
        a0 = w0 * f01.x; a1 = w0 * f01.y; a2 = w0 * f23.x; a3 = w0 * f23.y;
    }

    int e0 = g_offs[node];
    int e1 = e0 + indeg;
    int e = e0;
    for (; e + 8 <= e1; e += 8) {
        #pragma unroll
        for (int j = 0; j < 4; j++) {
            int2 r = g_csr[e + j * 2 + half];
            float nr = __int_as_float(r.y);
            uint2 u = *(const uint2*)&H[(size_t)r.x * 64 + c];
            float2 g01 = __half22float2(*(__half2*)&u.x);
            float2 g23 = __half22float2(*(__half2*)&u.y);
            a0 += nr * g01.x; a1 += nr * g01.y;
            a2 += nr * g23.x; a3 += nr * g23.y;
        }
    }
    for (; e < e1; e += 2) {
        int idx = e + half;
        int2 r = (idx < e1) ? g_csr[idx] : make_int2(node, 0);
        float nr = __int_as_float(r.y);
        uint2 u = *(const uint2*)&H[(size_t)r.x * 64 + c];
        float2 g01 = __half22float2(*(__half2*)&u.x);
        float2 g23 = __half22float2(*(__half2*)&u.y);
        a0 += nr * g01.x; a1 += nr * g01.y;
        a2 += nr * g23.x; a3 += nr * g23.y;
    }

    a0 += __shfl_xor_sync(0xffffffffu, a0, 16);
    a1 += __shfl_xor_sync(0xffffffffu, a1, 16);
    a2 += __shfl_xor_sync(0xffffffffu, a2, 16);
    a3 += __shfl_xor_sync(0xffffffffu, a3, 16);

    if (half == 0) {
        float o0 = fmaxf(b[c]     + dinv * a0, 0.f);
        float o1 = fmaxf(b[c + 1] + dinv * a1, 0.f);
        float o2 = fmaxf(b[c + 2] + dinv * a2, 0.f);
        float o3 = fmaxf(b[c + 3] + dinv * a3, 0.f);
        __half2 p0 = __floats2half2_rn(o0, o1);
        __half2 p1 = __floats2half2_rn(o2, o3);
        uint2 u = make_uint2(*(unsigned*)&p0, *(unsigned*)&p1);
        *(uint2*)&g_out_h[(size_t)node * 64 + c] = u;
    }
}

// ---------------- final aggregation (C=40, fp32 out, self-clean) -------------
__global__ void k_agg_final(const float* __restrict__ b, float* __restrict__ OUT,
                            int n) {
    constexpr int C = 40;
    const __half* H = (const __half*)g_h;

    int node = (blockIdx.x * blockDim.x + threadIdx.x) >> 5;
    int lane = threadIdx.x & 31;
    if (node >= n) return;
    int c = lane * 2;
    bool act = (c < C);

    int indeg = g_deg[node];
    float dinv = rsqrtf((float)(indeg + 1));

    float2 acc = make_float2(0.f, 0.f);
    if (act) {
        float2 hv = __half22float2(*(const __half2*)&H[(size_t)node * C + c]);
        acc.x = dinv * hv.x;
        acc.y = dinv * hv.y;
    }

    int e0 = g_offs[node];
    int e1 = e0 + indeg;
    int e = e0;
    for (; e + 4 <= e1; e += 4) {
        int2 r0 = g_csr[e];
        int2 r1 = g_csr[e + 1];
        int2 r2 = g_csr[e + 2];
        int2 r3 = g_csr[e + 3];
        if (act) {
            float2 h0 = __half22float2(*(const __half2*)&H[(size_t)r0.x * C + c]);
            float2 h1 = __half22float2(*(const __half2*)&H[(size_t)r1.x * C + c]);
            float2 h2 = __half22float2(*(const __half2*)&H[(size_t)r2.x * C + c]);
            float2 h3 = __half22float2(*(const __half2*)&H[(size_t)r3.x * C + c]);
            float n0 = __int_as_float(r0.y), n1 = __int_as_float(r1.y);
            float n2 = __int_as_float(r2.y), n3 = __int_as_float(r3.y);
            acc.x += n0 * h0.x; acc.y += n0 * h0.y;
            acc.x += n1 * h1.x; acc.y += n1 * h1.y;
            acc.x += n2 * h2.x; acc.y += n2 * h2.y;
            acc.x += n3 * h3.x; acc.y += n3 * h3.y;
        }
    }
    for (; e < e1; e++) {
        int2 r = g_csr[e];
        if (act) {
            float2 hv = __half22float2(*(const __half2*)&H[(size_t)r.x * C + c]);
            float nn = __int_as_float(r.y);
            acc.x += nn * hv.x; acc.y += nn * hv.y;
        }
    }
    if (act) {
        float ox = b[c]     + dinv * acc.x;
        float oy = b[c + 1] + dinv * acc.y;
        *(float2*)&OUT[(size_t)node * C + c] = make_float2(ox, oy);
    }
    if (lane == 0) g_deg[node] = 0;
    if (node == 0 && lane == 1) g_base = 0;
}

// ---------------- launcher ---------------------------------------------------
extern "C" void kernel_launch(void* const* d_in, const int* in_sizes, int n_in,
                              void* d_out, int out_size) {
    const float* x  = (const float*)d_in[0];
    const int*   ei = (const int*)d_in[1];
    const float* W1 = (const float*)d_in[2];
    const float* b1 = (const float*)d_in[3];
    const float* W2 = (const float*)d_in[4];
    const float* b2 = (const float*)d_in[5];
    const float* W3 = (const float*)d_in[6];
    const float* b3 = (const float*)d_in[7];
    float* out = (float*)d_out;

    int n = in_sizes[0] / CIN;
    int E = in_sizes[1] / 2;
    if (n > NMAX) n = NMAX;
    if (E > EMAX) E = EMAX;
    int nb = (n + 1023) / 1024;
    int eb4 = ((E + 3) / 4 + 255) / 256;

    static cudaStream_t s2 = nullptr;
    static cudaEvent_t evFork = nullptr, evJoin = nullptr;
    if (!s2) {
        cudaStreamCreate(&s2);
        cudaEventCreateWithFlags(&evFork, cudaEventDisableTiming);
        cudaEventCreateWithFlags(&evJoin, cudaEventDisableTiming);
    }

    cudaEventRecord(evFork, 0);
    cudaStreamWaitEvent(s2, evFork, 0);

    k_count<<<eb4, 256, 0, s2>>>(ei, E);
    k_scan<<<nb, 256, 0, s2>>>(n);
    k_fill_csr<<<eb4, 256, 0, s2>>>(ei, E);
    cudaEventRecord(evJoin, s2);

    k_gemm1<<<592, 256>>>(x, W1, n);

    cudaStreamWaitEvent(0, evJoin, 0);

    int agg_grid = (n + 7) / 8;

    k_agg64<<<agg_grid, 256>>>(b1, n);
    k_gemm_h<64, 64><<<592, 256>>>(W2, n);
    k_agg64<<<agg_grid, 256>>>(b2, n);
    k_gemm_h<64, 40><<<592, 160>>>(W3, n);
    k_agg_final<<<agg_grid, 256>>>(b3, out, n);
}